// round 11
// baseline (speedup 1.0000x reference)
#include <cuda_runtime.h>
#include <cstdint>

#ifndef NEG_INF_F
#define NEG_INF_F __int_as_float(0xff800000)
#endif

// Branchless strict-'>' insertion of (x, j) into the running top-4.
// Value-only compares keep the incumbent on ties == reference's
// smallest-index tie-break. Non-improving x -> exact no-op.
__device__ __forceinline__ void ins4(float x, int j,
                                     float& v0, float& v1, float& v2, float& v3,
                                     int& i0, int& i1, int& i2, int& i3)
{
    bool c0 = x > v0;
    bool c1 = x > v1;
    bool c2 = x > v2;
    bool c3 = x > v3;
    v3 = c3 ? (c2 ? v2 : x) : v3;   i3 = c3 ? (c2 ? i2 : j) : i3;
    v2 = c2 ? (c1 ? v1 : x) : v2;   i2 = c2 ? (c1 ? i1 : j) : i2;
    v1 = c1 ? (c0 ? v0 : x) : v1;   i1 = c1 ? (c0 ? i0 : j) : i1;
    v0 = c0 ? x : v0;               i0 = c0 ? j : i0;
}

__device__ __forceinline__ float4 ldcs4(const float4* p)
{
    return __ldcs(p);   // streaming: data is read exactly once
}

__device__ __forceinline__ void proc_pair(float4 a, float4 b, int j,
                                          float& v0, float& v1, float& v2, float& v3,
                                          int& i0, int& i1, int& i2, int& i3)
{
    float ma = fmaxf(fmaxf(fmaxf(a.x, a.y), a.z), a.w);
    float mb = fmaxf(fmaxf(fmaxf(b.x, b.y), b.z), b.w);
    if (ma > v3) {
        ins4(a.x, j + 0, v0, v1, v2, v3, i0, i1, i2, i3);
        ins4(a.y, j + 1, v0, v1, v2, v3, i0, i1, i2, i3);
        ins4(a.z, j + 2, v0, v1, v2, v3, i0, i1, i2, i3);
        ins4(a.w, j + 3, v0, v1, v2, v3, i0, i1, i2, i3);
    }
    if (mb > v3) {
        ins4(b.x, j + 4, v0, v1, v2, v3, i0, i1, i2, i3);
        ins4(b.y, j + 5, v0, v1, v2, v3, i0, i1, i2, i3);
        ins4(b.z, j + 6, v0, v1, v2, v3, i0, i1, i2, i3);
        ins4(b.w, j + 7, v0, v1, v2, v3, i0, i1, i2, i3);
    }
}

// One thread per node. Software-pipelined 8-edge body: iteration k+1's two
// LDG.128 issue before iteration k is processed, keeping loads in flight
// across the whole body. Per-quad max fast-reject (exact under strict '>').
__global__ void __launch_bounds__(256) segment_top4_kernel(
    const int* __restrict__ row_ptr,
    const float* __restrict__ scores,
    float* __restrict__ vals_out,   // [N,4] float32
    float* __restrict__ idxf_out,   // [N,4] float32 (index values; exact < 2^24)
    int n_nodes)
{
    int i = blockIdx.x * blockDim.x + threadIdx.x;
    if (i >= n_nodes) return;

    int s = __ldg(row_ptr + i);
    int e = __ldg(row_ptr + i + 1);

    float v0 = NEG_INF_F, v1 = NEG_INF_F, v2 = NEG_INF_F, v3 = NEG_INF_F;
    int   i0 = -1, i1 = -1, i2 = -1, i3 = -1;

    int j = s;

    // Scalar head to reach 16B alignment (scores base is 256B aligned).
    int head_end = (s + 3) & ~3;
    if (head_end > e) head_end = e;
    for (; j < head_end; ++j)
        ins4(__ldcs(scores + j), j, v0, v1, v2, v3, i0, i1, i2, i3);

    const float4* sv = reinterpret_cast<const float4*>(scores);
    int q = j >> 2;

    if (j + 8 <= e) {
        // Prime the pipeline.
        float4 a = ldcs4(sv + q);
        float4 b = ldcs4(sv + q + 1);
        // Steady state: prefetch next pair, then process current.
        while (j + 16 <= e) {
            float4 na = ldcs4(sv + q + 2);
            float4 nb = ldcs4(sv + q + 3);
            proc_pair(a, b, j, v0, v1, v2, v3, i0, i1, i2, i3);
            a = na; b = nb;
            j += 8; q += 2;
        }
        // Drain.
        proc_pair(a, b, j, v0, v1, v2, v3, i0, i1, i2, i3);
        j += 8; q += 2;
    }

    if (j + 4 <= e) {
        float4 a = ldcs4(sv + q);
        float ma = fmaxf(fmaxf(fmaxf(a.x, a.y), a.z), a.w);
        if (ma > v3) {
            ins4(a.x, j + 0, v0, v1, v2, v3, i0, i1, i2, i3);
            ins4(a.y, j + 1, v0, v1, v2, v3, i0, i1, i2, i3);
            ins4(a.z, j + 2, v0, v1, v2, v3, i0, i1, i2, i3);
            ins4(a.w, j + 3, v0, v1, v2, v3, i0, i1, i2, i3);
        }
        j += 4; q += 1;
    }

    for (; j < e; ++j)
        ins4(__ldcs(scores + j), j, v0, v1, v2, v3, i0, i1, i2, i3);

    // Coalesced 16B vector stores.
    reinterpret_cast<float4*>(vals_out)[i] = make_float4(v0, v1, v2, v3);
    reinterpret_cast<float4*>(idxf_out)[i] =
        make_float4((float)i0, (float)i1, (float)i2, (float)i3);
}

extern "C" void kernel_launch(void* const* d_in, const int* in_sizes, int n_in,
                              void* d_out, int out_size)
{
    // row_ptr is the smaller input (N+1) vs edge_scores (E).
    int a = in_sizes[0], b = (n_in > 1) ? in_sizes[1] : 0;
    int rp_slot = (n_in > 1 && b < a) ? 1 : 0;
    const int*   row_ptr = (const int*)d_in[rp_slot];
    const float* scores  = (const float*)d_in[1 - rp_slot];
    long long n = (long long)in_sizes[rp_slot] - 1;

    // Single-dtype (float32) output: vals [N,4] then idx-as-float [N,4].
    float* vals_out = (float*)d_out;
    float* idxf_out = vals_out + n * 4;

    int threads = 256;
    int blocks = (int)((n + threads - 1) / threads);
    segment_top4_kernel<<<blocks, threads>>>(row_ptr, scores, vals_out, idxf_out, (int)n);
}